// round 2
// baseline (speedup 1.0000x reference)
#include <cuda_runtime.h>
#include <math.h>

#define VD 256
#define VH 240
#define VW 320
#define NPIX (VH * VW)

// Per-pixel combined constant: (relu(max)+0.01) / sum_z exp(f[z,y,x])
__device__ float g_K[NPIX];

// ---------------------------------------------------------------------------
// Pass 1: per-pixel depth-softmax denominator, folded with the scale term.
// Threads map to pixels (x fastest) so each z-iteration is a fully coalesced
// 128B warp load at stride NPIX.
// ---------------------------------------------------------------------------
__global__ void __launch_bounds__(256) pass1_kernel(const float* __restrict__ fv,
                                                    const float* __restrict__ lmv) {
    int pix = blockIdx.x * blockDim.x + threadIdx.x;
    if (pix >= NPIX) return;
    const float* p = fv + pix;
    // 4 independent accumulators -> MLP 4+ on the strided loads
    float s0 = 0.f, s1 = 0.f, s2 = 0.f, s3 = 0.f;
#pragma unroll 8
    for (int z = 0; z < VD; z += 4) {
        s0 += __expf(p[(z + 0) * NPIX]);
        s1 += __expf(p[(z + 1) * NPIX]);
        s2 += __expf(p[(z + 2) * NPIX]);
        s3 += __expf(p[(z + 3) * NPIX]);
    }
    float s = (s0 + s1) + (s2 + s3);
    float mv = lmv[pix];
    float scale = (mv > 0.f ? mv : 0.f) + 0.01f;
    g_K[pix] = scale / s;
}

// ---------------------------------------------------------------------------
// Pass 2: project each 3D point, trilinear-sample density = exp(f)*K.
// One thread per point.
// ---------------------------------------------------------------------------
__global__ void __launch_bounds__(256) pass2_kernel(const float* __restrict__ fv,
                                                    const float* __restrict__ pts,
                                                    const float* __restrict__ intr,
                                                    const int* __restrict__ Hp,
                                                    const int* __restrict__ Wp,
                                                    const int* __restrict__ dminp,
                                                    const int* __restrict__ dmaxp,
                                                    float* __restrict__ out,
                                                    int n) {
    int i = blockIdx.x * blockDim.x + threadIdx.x;
    if (i >= n) return;

    float X = pts[3 * i + 0];
    float Y = pts[3 * i + 1];
    float Z = pts[3 * i + 2];

    float fx = intr[0], cx = intr[2];
    float fy = intr[4], cy = intr[5];
    float Himg = (float)(*Hp);
    float Wimg = (float)(*Wp);
    float dmin = (float)(*dminp);
    float dmax = (float)(*dmaxp);

    // projection: p2d = [fx*X + cx*Z, fy*Y + cy*Z, Z]
    float px = fx * X + cx * Z;
    float py = fy * Y + cy * Z;
    float pz = Z;
    float inv_e = 1.0f / (pz + 1e-10f);
    float inv = 1.0f / pz;

    float gx = (px * inv_e / Wimg - 0.5f) * 2.0f;
    float gy = (py * inv_e / Himg - 0.5f) * 2.0f;
    float gz = ((inv - dmin) / (dmax - dmin) - 0.5f) * 2.0f;

    // grid_sample: align_corners=True, padding=border
    float fxc = fminf(fmaxf((gx + 1.0f) * 0.5f * (float)(VW - 1), 0.0f), (float)(VW - 1));
    float fyc = fminf(fmaxf((gy + 1.0f) * 0.5f * (float)(VH - 1), 0.0f), (float)(VH - 1));
    float fzc = fminf(fmaxf((gz + 1.0f) * 0.5f * (float)(VD - 1), 0.0f), (float)(VD - 1));

    int x0 = (int)floorf(fxc); int x1 = min(x0 + 1, VW - 1);
    int y0 = (int)floorf(fyc); int y1 = min(y0 + 1, VH - 1);
    int z0 = (int)floorf(fzc); int z1 = min(z0 + 1, VD - 1);
    float wx = fxc - (float)x0;
    float wy = fyc - (float)y0;
    float wz = fzc - (float)z0;

    int p00 = y0 * VW + x0;
    int p01 = y0 * VW + x1;
    int p10 = y1 * VW + x0;
    int p11 = y1 * VW + x1;
    int zs0 = z0 * NPIX;
    int zs1 = z1 * NPIX;

    float K00 = g_K[p00];
    float K01 = g_K[p01];
    float K10 = g_K[p10];
    float K11 = g_K[p11];

    // density at the 8 corners
    float d000 = __expf(fv[zs0 + p00]) * K00;  // z0,y0,x0
    float d001 = __expf(fv[zs0 + p01]) * K01;  // z0,y0,x1
    float d010 = __expf(fv[zs0 + p10]) * K10;  // z0,y1,x0
    float d011 = __expf(fv[zs0 + p11]) * K11;  // z0,y1,x1
    float d100 = __expf(fv[zs1 + p00]) * K00;  // z1,y0,x0
    float d101 = __expf(fv[zs1 + p01]) * K01;  // z1,y0,x1
    float d110 = __expf(fv[zs1 + p10]) * K10;  // z1,y1,x0
    float d111 = __expf(fv[zs1 + p11]) * K11;  // z1,y1,x1

    float c00 = d000 + (d001 - d000) * wx;  // z0,y0
    float c01 = d010 + (d011 - d010) * wx;  // z0,y1
    float c10 = d100 + (d101 - d100) * wx;  // z1,y0
    float c11 = d110 + (d111 - d110) * wx;  // z1,y1
    float c0 = c00 + (c01 - c00) * wy;      // z0
    float c1 = c10 + (c11 - c10) * wy;      // z1
    out[i] = c0 + (c1 - c0) * wz;
}

extern "C" void kernel_launch(void* const* d_in, const int* in_sizes, int n_in,
                              void* d_out, int out_size) {
    const float* fv   = (const float*)d_in[0];  // feature_volume [1,1,256,240,320]
    const float* lmv  = (const float*)d_in[1];  // learnable_max_value [1,1,1,240,320]
    const float* intr = (const float*)d_in[2];  // [1,3,3]
    const float* pts  = (const float*)d_in[3];  // [1,8192,128,3]
    const int*   Hp   = (const int*)d_in[4];
    const int*   Wp   = (const int*)d_in[5];
    const int*   dmin = (const int*)d_in[6];
    const int*   dmax = (const int*)d_in[7];

    pass1_kernel<<<(NPIX + 255) / 256, 256>>>(fv, lmv);

    int n = out_size;  // 1*8192*128 points
    pass2_kernel<<<(n + 255) / 256, 256>>>(fv, pts, intr, Hp, Wp, dmin, dmax,
                                           (float*)d_out, n);
}